// round 2
// baseline (speedup 1.0000x reference)
#include <cuda_runtime.h>

// CapsuleLayer dynamic routing, fully fused per (batch, capsule) block.
// x: [256, 1152, 8] f32 ; W: [10, 1152, 8, 16] f32 ; out: [256, 10, 16] f32
#define NB 256
#define NC 10
#define NR 1152
#define IC 8
#define OC 16
#define THREADS 256
#define NWARP (THREADS / 32)
#define NUM_ITER 3

// SMEM layout (floats): P[OC][NR] | L[NR] | E[NR] | S[OC] | V[OC] | red[32]
#define SMEM_FLOATS (OC * NR + NR + NR + OC + OC + 32)

extern "C" __global__ void __launch_bounds__(THREADS, 2)
caps_route_kernel(const float* __restrict__ x,
                  const float* __restrict__ W,
                  float* __restrict__ out)
{
    extern __shared__ float sm[];
    float* P   = sm;                       // priors, transposed [oc][r]
    float* L   = P + OC * NR;              // logits[r]
    float* E   = L + NR;                   // exp buffer
    float* S   = E + NR;                   // pre-squash sum s[oc]
    float* V   = S + OC;                   // squashed output v[oc]
    float* red = V + OC;                   // reduction scratch

    const int b    = blockIdx.x;
    const int c    = blockIdx.y;
    const int tid  = threadIdx.x;
    const int lane = tid & 31;
    const int wid  = tid >> 5;

    // ---------------- Phase 1: priors into SMEM (transposed) ----------------
    // prior[r][o] = sum_i x[b,r,i] * W[c,r,i,o]
    const float* xb = x + (size_t)b * NR * IC;
    const float* Wc = W + (size_t)c * NR * IC * OC;

    for (int r = tid; r < NR; r += THREADS) {
        float4 xv0 = *reinterpret_cast<const float4*>(xb + r * IC);
        float4 xv1 = *reinterpret_cast<const float4*>(xb + r * IC + 4);
        float xs[IC] = {xv0.x, xv0.y, xv0.z, xv0.w, xv1.x, xv1.y, xv1.z, xv1.w};

        const float4* wr = reinterpret_cast<const float4*>(Wc + (size_t)r * IC * OC);
        float acc[OC];
        #pragma unroll
        for (int o = 0; o < OC; ++o) acc[o] = 0.f;

        #pragma unroll
        for (int i = 0; i < IC; ++i) {
            float xi = xs[i];
            float4 w0 = wr[i * 4 + 0];
            float4 w1 = wr[i * 4 + 1];
            float4 w2 = wr[i * 4 + 2];
            float4 w3 = wr[i * 4 + 3];
            acc[0]  = fmaf(xi, w0.x, acc[0]);
            acc[1]  = fmaf(xi, w0.y, acc[1]);
            acc[2]  = fmaf(xi, w0.z, acc[2]);
            acc[3]  = fmaf(xi, w0.w, acc[3]);
            acc[4]  = fmaf(xi, w1.x, acc[4]);
            acc[5]  = fmaf(xi, w1.y, acc[5]);
            acc[6]  = fmaf(xi, w1.z, acc[6]);
            acc[7]  = fmaf(xi, w1.w, acc[7]);
            acc[8]  = fmaf(xi, w2.x, acc[8]);
            acc[9]  = fmaf(xi, w2.y, acc[9]);
            acc[10] = fmaf(xi, w2.z, acc[10]);
            acc[11] = fmaf(xi, w2.w, acc[11]);
            acc[12] = fmaf(xi, w3.x, acc[12]);
            acc[13] = fmaf(xi, w3.y, acc[13]);
            acc[14] = fmaf(xi, w3.z, acc[14]);
            acc[15] = fmaf(xi, w3.w, acc[15]);
        }
        #pragma unroll
        for (int o = 0; o < OC; ++o) P[o * NR + r] = acc[o];
        L[r] = 0.f;
    }
    __syncthreads();

    // ---------------- Phase 2: routing iterations ----------------
    const float inv_nr = 1.0f / (float)NR;
    float pscale = 0.f;  // 1/sum(exp) for iters > 0

    for (int iter = 0; iter < NUM_ITER; ++iter) {
        if (iter > 0) {
            // softmax over r: max
            float lm = -1e30f;
            for (int r = tid; r < NR; r += THREADS) lm = fmaxf(lm, L[r]);
            #pragma unroll
            for (int off = 16; off > 0; off >>= 1)
                lm = fmaxf(lm, __shfl_xor_sync(0xFFFFFFFFu, lm, off));
            if (lane == 0) red[wid] = lm;
            __syncthreads();
            if (wid == 0) {
                float v = (lane < NWARP) ? red[lane] : -1e30f;
                #pragma unroll
                for (int off = 4; off > 0; off >>= 1)
                    v = fmaxf(v, __shfl_xor_sync(0xFFFFFFFFu, v, off));
                if (lane == 0) red[16] = v;
            }
            __syncthreads();
            float m = red[16];

            // exp + sum
            float ls = 0.f;
            for (int r = tid; r < NR; r += THREADS) {
                float e = __expf(L[r] - m);
                E[r] = e;
                ls += e;
            }
            #pragma unroll
            for (int off = 16; off > 0; off >>= 1)
                ls += __shfl_xor_sync(0xFFFFFFFFu, ls, off);
            if (lane == 0) red[8 + wid] = ls;
            __syncthreads();
            if (wid == 0) {
                float v = (lane < NWARP) ? red[8 + lane] : 0.f;
                #pragma unroll
                for (int off = 4; off > 0; off >>= 1)
                    v += __shfl_xor_sync(0xFFFFFFFFu, v, off);
                if (lane == 0) red[17] = 1.0f / v;
            }
            __syncthreads();
            pscale = red[17];
        }

        // weighted sum s[oc] = sum_r p_r * prior[oc][r]; warp wid owns oc = 2*wid, 2*wid+1
        const int o0 = wid * 2, o1 = wid * 2 + 1;
        const float* P0 = P + o0 * NR;
        const float* P1 = P + o1 * NR;
        float a0 = 0.f, a1 = 0.f;
        if (iter == 0) {
            for (int r = lane; r < NR; r += 32) { a0 += P0[r]; a1 += P1[r]; }
            a0 *= inv_nr; a1 *= inv_nr;
        } else {
            for (int r = lane; r < NR; r += 32) {
                float p = E[r];
                a0 = fmaf(p, P0[r], a0);
                a1 = fmaf(p, P1[r], a1);
            }
            a0 *= pscale; a1 *= pscale;
        }
        #pragma unroll
        for (int off = 16; off > 0; off >>= 1) {
            a0 += __shfl_xor_sync(0xFFFFFFFFu, a0, off);
            a1 += __shfl_xor_sync(0xFFFFFFFFu, a1, off);
        }
        if (lane == 0) { S[o0] = a0; S[o1] = a1; }
        __syncthreads();

        // squash (warp 0): v = (sq/(1+sq)) * s / sqrt(sq), sq = sum_oc s^2
        if (wid == 0) {
            float t  = (lane < OC) ? S[lane] : 0.f;
            float sq = t * t;
            #pragma unroll
            for (int off = 16; off > 0; off >>= 1)
                sq += __shfl_xor_sync(0xFFFFFFFFu, sq, off);
            float scale = sq / ((1.f + sq) * sqrtf(sq));
            if (lane < OC) V[lane] = t * scale;
        }
        __syncthreads();

        // delta logits (skip on last iteration)
        if (iter < NUM_ITER - 1) {
            float v[OC];
            #pragma unroll
            for (int o = 0; o < OC; ++o) v[o] = V[o];
            for (int r = tid; r < NR; r += THREADS) {
                float d = 0.f;
                #pragma unroll
                for (int o = 0; o < OC; ++o)
                    d = fmaf(P[o * NR + r], v[o], d);
                L[r] += d;
            }
            __syncthreads();
        }
    }

    // ---------------- Phase 3: output ----------------
    if (tid < OC)
        out[((size_t)b * NC + c) * OC + tid] = V[tid];
}

extern "C" void kernel_launch(void* const* d_in, const int* in_sizes, int n_in,
                              void* d_out, int out_size)
{
    (void)in_sizes; (void)n_in; (void)out_size;
    const float* x = (const float*)d_in[0];
    const float* W = (const float*)d_in[1];
    float* out = (float*)d_out;

    static int smem_set = 0;
    const int smem_bytes = SMEM_FLOATS * sizeof(float);
    if (!smem_set) {
        cudaFuncSetAttribute(caps_route_kernel,
                             cudaFuncAttributeMaxDynamicSharedMemorySize,
                             smem_bytes);
        smem_set = 1;
    }

    dim3 grid(NB, NC);
    caps_route_kernel<<<grid, THREADS, smem_bytes>>>(x, W, out);
}

// round 3
// speedup vs baseline: 1.2836x; 1.2836x over previous
#include <cuda_runtime.h>

// CapsuleLayer dynamic routing, fused, batch-tiled (BT=2) per block.
// x: [256, 1152, 8] f32 ; W: [10, 1152, 8, 16] f32 ; out: [256, 10, 16] f32
#define NB 256
#define NC 10
#define NR 1152
#define IC 8
#define OC 16
#define THREADS 288
#define NWARP 9
#define BT 2
#define RPT 4              // rows per thread in routing (NR / THREADS)
#define ROWS_PER_WARP 128  // NR / NWARP
#define PSTRIDE 20         // padded prior-row stride (floats), bank-conflict-free
#define NUM_ITER 3

// SMEM floats: P0[NR][PSTRIDE] | P1[NR][PSTRIDE] | red[NWARP*32] | V[32] | aux[24]
#define SMEM_FLOATS (2 * NR * PSTRIDE + NWARP * 32 + 32 + 24)

extern "C" __global__ void __launch_bounds__(THREADS, 1)
caps_route_kernel(const float* __restrict__ x,
                  const float* __restrict__ W,
                  float* __restrict__ out)
{
    extern __shared__ float sm[];
    float* P0  = sm;                      // priors batch 0, [r][16] padded to 20
    float* P1  = P0 + NR * PSTRIDE;       // priors batch 1
    float* red = P1 + NR * PSTRIDE;       // [NWARP][32] block-reduce scratch
    float* V   = red + NWARP * 32;        // squashed outputs: [0..15]=b0, [16..31]=b1
    float* aux = V + 32;                  // softmax reduce scratch

    const int tid  = threadIdx.x;
    const int lane = tid & 31;
    const int wid  = tid >> 5;

    const int b0 = blockIdx.x * BT;
    const int c  = blockIdx.y;

    const float* xb0 = x + (size_t)b0 * NR * IC;
    const float* xb1 = xb0 + NR * IC;
    const float* Wc  = W + (size_t)c * NR * IC * OC;

    // ============ Phase 1: priors (warp-cooperative, coalesced W) ============
    // Warp w owns rows [w*128, (w+1)*128). One LDG.128 per warp loads a full
    // 512B W row. Lane l holds W[r][i=l>>2][o=(l&3)*4 .. +3].
    {
        const int i_lane = lane >> 2;
        const int rbase  = wid * ROWS_PER_WARP;

        for (int rr = 0; rr < ROWS_PER_WARP; rr += 4) {
            float4 wr[4];
            float  xa[4], xc[4];
            #pragma unroll
            for (int u = 0; u < 4; ++u) {
                const int r = rbase + rr + u;
                wr[u] = reinterpret_cast<const float4*>(Wc + (size_t)r * (IC * OC))[lane];
                xa[u] = xb0[r * IC + i_lane];
                xc[u] = xb1[r * IC + i_lane];
            }
            #pragma unroll
            for (int u = 0; u < 4; ++u) {
                const int r = rbase + rr + u;
                float4 a0, a1;
                a0.x = wr[u].x * xa[u]; a0.y = wr[u].y * xa[u];
                a0.z = wr[u].z * xa[u]; a0.w = wr[u].w * xa[u];
                a1.x = wr[u].x * xc[u]; a1.y = wr[u].y * xc[u];
                a1.z = wr[u].z * xc[u]; a1.w = wr[u].w * xc[u];
                // reduce over i (lanes differing in bits 2..4)
                #pragma unroll
                for (int off = 4; off <= 16; off <<= 1) {
                    a0.x += __shfl_xor_sync(0xFFFFFFFFu, a0.x, off);
                    a0.y += __shfl_xor_sync(0xFFFFFFFFu, a0.y, off);
                    a0.z += __shfl_xor_sync(0xFFFFFFFFu, a0.z, off);
                    a0.w += __shfl_xor_sync(0xFFFFFFFFu, a0.w, off);
                    a1.x += __shfl_xor_sync(0xFFFFFFFFu, a1.x, off);
                    a1.y += __shfl_xor_sync(0xFFFFFFFFu, a1.y, off);
                    a1.z += __shfl_xor_sync(0xFFFFFFFFu, a1.z, off);
                    a1.w += __shfl_xor_sync(0xFFFFFFFFu, a1.w, off);
                }
                if (lane < 4) {
                    reinterpret_cast<float4*>(P0 + r * PSTRIDE)[lane] = a0;
                    reinterpret_cast<float4*>(P1 + r * PSTRIDE)[lane] = a1;
                }
            }
        }
    }
    __syncthreads();

    // ============ Phase 2: routing (logits/probs register-resident) ============
    // Thread t owns rows r = t + k*THREADS, k=0..3, for BOTH batches.
    float L0[RPT], L1[RPT];     // logits
    float pr0[RPT], pr1[RPT];   // unnormalized probs (exp)
    #pragma unroll
    for (int k = 0; k < RPT; ++k) { L0[k] = 0.f; L1[k] = 0.f; }

    const float inv_nr = 1.0f / (float)NR;

    for (int iter = 0; iter < NUM_ITER; ++iter) {
        float pscale0, pscale1;
        if (iter == 0) {
            #pragma unroll
            for (int k = 0; k < RPT; ++k) { pr0[k] = 1.f; pr1[k] = 1.f; }
            pscale0 = inv_nr; pscale1 = inv_nr;
        } else {
            // --- softmax max ---
            float m0 = -1e30f, m1 = -1e30f;
            #pragma unroll
            for (int k = 0; k < RPT; ++k) {
                m0 = fmaxf(m0, L0[k]); m1 = fmaxf(m1, L1[k]);
            }
            #pragma unroll
            for (int off = 16; off > 0; off >>= 1) {
                m0 = fmaxf(m0, __shfl_xor_sync(0xFFFFFFFFu, m0, off));
                m1 = fmaxf(m1, __shfl_xor_sync(0xFFFFFFFFu, m1, off));
            }
            if (lane == 0) { aux[wid] = m0; aux[NWARP + wid] = m1; }
            __syncthreads();
            if (wid == 0) {
                float v0 = (lane < NWARP) ? aux[lane] : -1e30f;
                float v1 = (lane < NWARP) ? aux[NWARP + lane] : -1e30f;
                #pragma unroll
                for (int off = 8; off > 0; off >>= 1) {
                    v0 = fmaxf(v0, __shfl_xor_sync(0xFFFFFFFFu, v0, off));
                    v1 = fmaxf(v1, __shfl_xor_sync(0xFFFFFFFFu, v1, off));
                }
                if (lane == 0) { aux[20] = v0; aux[21] = v1; }
            }
            __syncthreads();
            m0 = aux[20]; m1 = aux[21];
            __syncthreads();   // protect aux before sum-stage rewrite

            // --- exp + sum ---
            float s0 = 0.f, s1 = 0.f;
            #pragma unroll
            for (int k = 0; k < RPT; ++k) {
                pr0[k] = __expf(L0[k] - m0); s0 += pr0[k];
                pr1[k] = __expf(L1[k] - m1); s1 += pr1[k];
            }
            #pragma unroll
            for (int off = 16; off > 0; off >>= 1) {
                s0 += __shfl_xor_sync(0xFFFFFFFFu, s0, off);
                s1 += __shfl_xor_sync(0xFFFFFFFFu, s1, off);
            }
            if (lane == 0) { aux[wid] = s0; aux[NWARP + wid] = s1; }
            __syncthreads();
            if (wid == 0) {
                float v0 = (lane < NWARP) ? aux[lane] : 0.f;
                float v1 = (lane < NWARP) ? aux[NWARP + lane] : 0.f;
                #pragma unroll
                for (int off = 8; off > 0; off >>= 1) {
                    v0 += __shfl_xor_sync(0xFFFFFFFFu, v0, off);
                    v1 += __shfl_xor_sync(0xFFFFFFFFu, v1, off);
                }
                if (lane == 0) { aux[20] = 1.0f / v0; aux[21] = 1.0f / v1; }
            }
            __syncthreads();
            pscale0 = aux[20]; pscale1 = aux[21];
        }

        // --- weighted sum: s[b][oc] = sum_r p_r * prior[b][r][oc] ---
        float a0[OC], a1[OC];
        #pragma unroll
        for (int j = 0; j < OC; ++j) { a0[j] = 0.f; a1[j] = 0.f; }
        #pragma unroll
        for (int k = 0; k < RPT; ++k) {
            const int r = tid + k * THREADS;
            const float4* p0 = reinterpret_cast<const float4*>(P0 + r * PSTRIDE);
            const float4* p1 = reinterpret_cast<const float4*>(P1 + r * PSTRIDE);
            const float q0 = pr0[k], q1 = pr1[k];
            #pragma unroll
            for (int j4 = 0; j4 < 4; ++j4) {
                float4 t0 = p0[j4];
                float4 t1 = p1[j4];
                a0[j4*4+0] = fmaf(q0, t0.x, a0[j4*4+0]);
                a0[j4*4+1] = fmaf(q0, t0.y, a0[j4*4+1]);
                a0[j4*4+2] = fmaf(q0, t0.z, a0[j4*4+2]);
                a0[j4*4+3] = fmaf(q0, t0.w, a0[j4*4+3]);
                a1[j4*4+0] = fmaf(q1, t1.x, a1[j4*4+0]);
                a1[j4*4+1] = fmaf(q1, t1.y, a1[j4*4+1]);
                a1[j4*4+2] = fmaf(q1, t1.z, a1[j4*4+2]);
                a1[j4*4+3] = fmaf(q1, t1.w, a1[j4*4+3]);
            }
        }
        // intra-warp reduce all 32 accumulators
        #pragma unroll
        for (int off = 16; off > 0; off >>= 1) {
            #pragma unroll
            for (int j = 0; j < OC; ++j) {
                a0[j] += __shfl_xor_sync(0xFFFFFFFFu, a0[j], off);
                a1[j] += __shfl_xor_sync(0xFFFFFFFFu, a1[j], off);
            }
        }
        if (lane == 0) {
            #pragma unroll
            for (int j = 0; j < OC; ++j) {
                red[wid * 32 + j]      = a0[j];
                red[wid * 32 + 16 + j] = a1[j];
            }
        }
        __syncthreads();

        // --- inter-warp reduce + squash, warp 0; lanes 0-15 = b0, 16-31 = b1 ---
        if (wid == 0) {
            float sv = 0.f;
            #pragma unroll
            for (int w = 0; w < NWARP; ++w) sv += red[w * 32 + lane];
            sv *= (lane < 16) ? pscale0 : pscale1;
            float sq = sv * sv;
            #pragma unroll
            for (int off = 8; off > 0; off >>= 1)
                sq += __shfl_xor_sync(0xFFFFFFFFu, sq, off);   // stays within 16-lane half
            const float scale = sq / ((1.f + sq) * sqrtf(sq));
            V[lane] = sv * scale;
        }
        __syncthreads();

        // --- delta logits (skip on last iter) ---
        if (iter < NUM_ITER - 1) {
            const float4 v00 = *reinterpret_cast<const float4*>(V + 0);
            const float4 v01 = *reinterpret_cast<const float4*>(V + 4);
            const float4 v02 = *reinterpret_cast<const float4*>(V + 8);
            const float4 v03 = *reinterpret_cast<const float4*>(V + 12);
            const float4 v10 = *reinterpret_cast<const float4*>(V + 16);
            const float4 v11 = *reinterpret_cast<const float4*>(V + 20);
            const float4 v12 = *reinterpret_cast<const float4*>(V + 24);
            const float4 v13 = *reinterpret_cast<const float4*>(V + 28);
            #pragma unroll
            for (int k = 0; k < RPT; ++k) {
                const int r = tid + k * THREADS;
                const float4* p0 = reinterpret_cast<const float4*>(P0 + r * PSTRIDE);
                const float4* p1 = reinterpret_cast<const float4*>(P1 + r * PSTRIDE);
                float4 t;
                float d0 = 0.f, d1 = 0.f;
                t = p0[0]; d0 = fmaf(t.x, v00.x, d0); d0 = fmaf(t.y, v00.y, d0);
                           d0 = fmaf(t.z, v00.z, d0); d0 = fmaf(t.w, v00.w, d0);
                t = p0[1]; d0 = fmaf(t.x, v01.x, d0); d0 = fmaf(t.y, v01.y, d0);
                           d0 = fmaf(t.z, v01.z, d0); d0 = fmaf(t.w, v01.w, d0);
                t = p0[2]; d0 = fmaf(t.x, v02.x, d0); d0 = fmaf(t.y, v02.y, d0);
                           d0 = fmaf(t.z, v02.z, d0); d0 = fmaf(t.w, v02.w, d0);
                t = p0[3]; d0 = fmaf(t.x, v03.x, d0); d0 = fmaf(t.y, v03.y, d0);
                           d0 = fmaf(t.z, v03.z, d0); d0 = fmaf(t.w, v03.w, d0);
                t = p1[0]; d1 = fmaf(t.x, v10.x, d1); d1 = fmaf(t.y, v10.y, d1);
                           d1 = fmaf(t.z, v10.z, d1); d1 = fmaf(t.w, v10.w, d1);
                t = p1[1]; d1 = fmaf(t.x, v11.x, d1); d1 = fmaf(t.y, v11.y, d1);
                           d1 = fmaf(t.z, v11.z, d1); d1 = fmaf(t.w, v11.w, d1);
                t = p1[2]; d1 = fmaf(t.x, v12.x, d1); d1 = fmaf(t.y, v12.y, d1);
                           d1 = fmaf(t.z, v12.z, d1); d1 = fmaf(t.w, v12.w, d1);
                t = p1[3]; d1 = fmaf(t.x, v13.x, d1); d1 = fmaf(t.y, v13.y, d1);
                           d1 = fmaf(t.z, v13.z, d1); d1 = fmaf(t.w, v13.w, d1);
                L0[k] += d0;
                L1[k] += d1;
            }
        }
    }

    // ============ Phase 3: output ============
    if (tid < 2 * OC) {
        const int bb = b0 + (tid >> 4);
        out[((size_t)bb * NC + c) * OC + (tid & 15)] = V[tid];
    }
}

extern "C" void kernel_launch(void* const* d_in, const int* in_sizes, int n_in,
                              void* d_out, int out_size)
{
    (void)in_sizes; (void)n_in; (void)out_size;
    const float* x = (const float*)d_in[0];
    const float* W = (const float*)d_in[1];
    float* out = (float*)d_out;

    static int smem_set = 0;
    const int smem_bytes = SMEM_FLOATS * sizeof(float);
    if (!smem_set) {
        cudaFuncSetAttribute(caps_route_kernel,
                             cudaFuncAttributeMaxDynamicSharedMemorySize,
                             smem_bytes);
        smem_set = 1;
    }

    dim3 grid(NB / BT, NC);
    caps_route_kernel<<<grid, THREADS, smem_bytes>>>(x, W, out);
}

// round 5
// speedup vs baseline: 2.3952x; 1.8659x over previous
#include <cuda_runtime.h>

// CapsuleLayer dynamic routing — SMEM-staged W, shuffle-free priors, BT=2.
// x: [256, 1152, 8] f32 ; W: [10, 1152, 8, 16] f32 ; out: [256, 10, 16] f32
#define NB 256
#define NC 10
#define NR 1152
#define IC 8
#define OC 16
#define THREADS 512
#define NWARP 16
#define BT 2
#define CH 128             // rows per chunk
#define NCH 9              // NR / CH
#define WSTR4 36           // Wbuf row stride in float4 (144 floats, ≡16 mod 32)
#define PSTR 1154          // P row stride in floats (≡2 mod 32)
#define NUM_ITER 3

// SMEM floats: P0[16][PSTR] | P1[16][PSTR] | Wbuf[CH][144] | E0[NR] | E1[NR]
//            | S[32] | V[32] | red[32] | aux[8]
#define P_FLOATS   (OC * PSTR)
#define W_FLOATS   (CH * WSTR4 * 4)
#define SMEM_FLOATS (2 * P_FLOATS + W_FLOATS + 2 * NR + 32 + 32 + 32 + 8)

extern "C" __global__ void __launch_bounds__(THREADS, 1)
caps_route_kernel(const float* __restrict__ x,
                  const float* __restrict__ W,
                  float* __restrict__ out)
{
    extern __shared__ float sm[];
    float*  P0   = sm;                        // [oc][r] transposed priors, batch 0
    float*  P1   = P0 + P_FLOATS;             // batch 1
    float4* Wbuf = reinterpret_cast<float4*>(P1 + P_FLOATS);
    float*  E0   = P1 + P_FLOATS + W_FLOATS;  // probs batch 0
    float*  E1   = E0 + NR;
    float*  S    = E1 + NR;                   // pre-squash sums [0..15]=b0,[16..31]=b1
    float*  V    = S + 32;                    // squashed outputs
    float*  red  = V + 32;                    // per-warp reduce scratch
    float*  aux  = red + 32;                  // block-level scalars

    const int tid  = threadIdx.x;
    const int lane = tid & 31;
    const int wid  = tid >> 5;

    const int b0 = blockIdx.x * BT;
    const int c  = blockIdx.y;

    const float*  xb0 = x + (size_t)b0 * NR * IC;
    const float*  xb1 = xb0 + NR * IC;
    const float4* Wc4 = reinterpret_cast<const float4*>(
                            W + (size_t)c * NR * IC * OC);

    // ================= Phase 1: priors (shuffle-free, SMEM-staged W) =========
    // Chunk = 128 W rows (128*128 floats = 4096 float4). All 512 threads load
    // 8 float4 each (coalesced), STS into Wbuf. Then thread (row=tid>>2,
    // sub=tid&3) computes oc-quad sub*4..sub*4+3 for BOTH batches of its row.
    const int row_l = tid >> 2;     // 0..127
    const int sub   = tid & 3;      // oc quad

    float4 wreg[8];
    #pragma unroll
    for (int n = 0; n < 8; ++n)
        wreg[n] = Wc4[n * THREADS + tid];          // chunk 0

    for (int ch = 0; ch < NCH; ++ch) {
        #pragma unroll
        for (int n = 0; n < 8; ++n) {
            const int idx = n * THREADS + tid;     // 0..4095
            Wbuf[(idx >> 5) * WSTR4 + (idx & 31)] = wreg[n];
        }
        const int r = ch * CH + row_l;
        // x rows for this thread's row (both batches) — issue before sync
        const float4 xa0 = reinterpret_cast<const float4*>(xb0 + r * IC)[0];
        const float4 xa1 = reinterpret_cast<const float4*>(xb0 + r * IC)[1];
        const float4 xc0 = reinterpret_cast<const float4*>(xb1 + r * IC)[0];
        const float4 xc1 = reinterpret_cast<const float4*>(xb1 + r * IC)[1];
        __syncthreads();

        if (ch < NCH - 1) {
            #pragma unroll
            for (int n = 0; n < 8; ++n)
                wreg[n] = Wc4[(ch + 1) * (CH * 32) + n * THREADS + tid];
        }

        const float xA[8] = {xa0.x, xa0.y, xa0.z, xa0.w, xa1.x, xa1.y, xa1.z, xa1.w};
        const float xB[8] = {xc0.x, xc0.y, xc0.z, xc0.w, xc1.x, xc1.y, xc1.z, xc1.w};

        float aA0 = 0.f, aA1 = 0.f, aA2 = 0.f, aA3 = 0.f;
        float aB0 = 0.f, aB1 = 0.f, aB2 = 0.f, aB3 = 0.f;
        #pragma unroll
        for (int i = 0; i < IC; ++i) {
            const float4 w = Wbuf[row_l * WSTR4 + i * 4 + sub];
            aA0 = fmaf(xA[i], w.x, aA0);
            aA1 = fmaf(xA[i], w.y, aA1);
            aA2 = fmaf(xA[i], w.z, aA2);
            aA3 = fmaf(xA[i], w.w, aA3);
            aB0 = fmaf(xB[i], w.x, aB0);
            aB1 = fmaf(xB[i], w.y, aB1);
            aB2 = fmaf(xB[i], w.z, aB2);
            aB3 = fmaf(xB[i], w.w, aB3);
        }
        const int ob = sub * 4;
        P0[(ob + 0) * PSTR + r] = aA0;
        P0[(ob + 1) * PSTR + r] = aA1;
        P0[(ob + 2) * PSTR + r] = aA2;
        P0[(ob + 3) * PSTR + r] = aA3;
        P1[(ob + 0) * PSTR + r] = aB0;
        P1[(ob + 1) * PSTR + r] = aB1;
        P1[(ob + 2) * PSTR + r] = aB2;
        P1[(ob + 3) * PSTR + r] = aB3;
        __syncthreads();
    }

    // ================= Phase 2: routing iterations ===========================
    // Thread owns logit rows: tid, tid+512, tid+1024 (last only if tid < 128).
    const int  r0v = tid;
    const int  r1v = tid + THREADS;
    const int  r2v = tid + 2 * THREADS;
    const bool has3 = (r2v < NR);

    float L0[3] = {0.f, 0.f, 0.f};
    float L1[3] = {0.f, 0.f, 0.f};

    const float inv_nr = 1.0f / (float)NR;

    for (int iter = 0; iter < NUM_ITER; ++iter) {
        if (iter > 0) {
            // ---- softmax over r (both batches) ----
            float m0 = fmaxf(L0[0], L0[1]);
            float m1 = fmaxf(L1[0], L1[1]);
            if (has3) { m0 = fmaxf(m0, L0[2]); m1 = fmaxf(m1, L1[2]); }
            #pragma unroll
            for (int off = 16; off > 0; off >>= 1) {
                m0 = fmaxf(m0, __shfl_xor_sync(0xFFFFFFFFu, m0, off));
                m1 = fmaxf(m1, __shfl_xor_sync(0xFFFFFFFFu, m1, off));
            }
            if (lane == 0) { red[wid] = m0; red[16 + wid] = m1; }
            __syncthreads();
            if (wid == 0) {
                float v = red[lane];           // 0..15 = b0 maxes, 16..31 = b1
                #pragma unroll
                for (int off = 8; off > 0; off >>= 1)
                    v = fmaxf(v, __shfl_xor_sync(0xFFFFFFFFu, v, off));
                if ((lane & 15) == 0) aux[lane >> 4] = v;
            }
            __syncthreads();
            m0 = aux[0]; m1 = aux[1];
            __syncthreads();                   // red about to be rewritten

            float s0, s1;
            {
                const float e00 = __expf(L0[0] - m0);
                const float e01 = __expf(L0[1] - m0);
                const float e10 = __expf(L1[0] - m1);
                const float e11 = __expf(L1[1] - m1);
                E0[r0v] = e00; E0[r1v] = e01;
                E1[r0v] = e10; E1[r1v] = e11;
                s0 = e00 + e01; s1 = e10 + e11;
                if (has3) {
                    const float e02 = __expf(L0[2] - m0);
                    const float e12 = __expf(L1[2] - m1);
                    E0[r2v] = e02; E1[r2v] = e12;
                    s0 += e02; s1 += e12;
                }
            }
            #pragma unroll
            for (int off = 16; off > 0; off >>= 1) {
                s0 += __shfl_xor_sync(0xFFFFFFFFu, s0, off);
                s1 += __shfl_xor_sync(0xFFFFFFFFu, s1, off);
            }
            if (lane == 0) { red[wid] = s0; red[16 + wid] = s1; }
            __syncthreads();
            if (wid == 0) {
                float v = red[lane];
                #pragma unroll
                for (int off = 8; off > 0; off >>= 1)
                    v += __shfl_xor_sync(0xFFFFFFFFu, v, off);
                if ((lane & 15) == 0) aux[2 + (lane >> 4)] = 1.0f / v;
            }
            __syncthreads();
        }

        // ---- weighted sum: warp w handles oc=w, both batches (stride-1 LDS) --
        {
            const float* p0 = P0 + wid * PSTR;
            const float* p1 = P1 + wid * PSTR;
            float a0 = 0.f, a1 = 0.f;
            if (iter == 0) {
                #pragma unroll 4
                for (int rr = lane; rr < NR; rr += 32) {
                    a0 += p0[rr];
                    a1 += p1[rr];
                }
            } else {
                #pragma unroll 4
                for (int rr = lane; rr < NR; rr += 32) {
                    a0 = fmaf(E0[rr], p0[rr], a0);
                    a1 = fmaf(E1[rr], p1[rr], a1);
                }
            }
            #pragma unroll
            for (int off = 16; off > 0; off >>= 1) {
                a0 += __shfl_xor_sync(0xFFFFFFFFu, a0, off);
                a1 += __shfl_xor_sync(0xFFFFFFFFu, a1, off);
            }
            if (lane == 0) { S[wid] = a0; S[16 + wid] = a1; }
        }
        __syncthreads();

        // ---- squash (warp 0, lanes 0-15 = b0, 16-31 = b1) ----
        if (wid == 0) {
            float sv = S[lane];
            const float ps = (iter == 0) ? inv_nr : aux[2 + (lane >> 4)];
            sv *= ps;
            float sq = sv * sv;
            #pragma unroll
            for (int off = 8; off > 0; off >>= 1)
                sq += __shfl_xor_sync(0xFFFFFFFFu, sq, off);  // within 16-half
            const float scale = sq / ((1.f + sq) * sqrtf(sq));
            V[lane] = sv * scale;
        }
        __syncthreads();

        // ---- delta logits (skip on last iteration) ----
        if (iter < NUM_ITER - 1) {
            float v0[OC], v1[OC];
            #pragma unroll
            for (int o = 0; o < OC; ++o) { v0[o] = V[o]; v1[o] = V[16 + o]; }

            float d00 = 0.f, d01 = 0.f, d02 = 0.f;
            float d10 = 0.f, d11 = 0.f, d12 = 0.f;
            #pragma unroll
            for (int o = 0; o < OC; ++o) {
                const float* p0 = P0 + o * PSTR;
                const float* p1 = P1 + o * PSTR;
                d00 = fmaf(p0[r0v], v0[o], d00);
                d01 = fmaf(p0[r1v], v0[o], d01);
                d10 = fmaf(p1[r0v], v1[o], d10);
                d11 = fmaf(p1[r1v], v1[o], d11);
                if (has3) {
                    d02 = fmaf(p0[r2v], v0[o], d02);
                    d12 = fmaf(p1[r2v], v1[o], d12);
                }
            }
            L0[0] += d00; L0[1] += d01; L0[2] += d02;
            L1[0] += d10; L1[1] += d11; L1[2] += d12;
        }
    }

    // ================= Phase 3: output =======================================
    if (tid < 2 * OC) {
        const int bb = b0 + (tid >> 4);
        out[((size_t)bb * NC + c) * OC + (tid & 15)] = V[tid];
    }
}

extern "C" void kernel_launch(void* const* d_in, const int* in_sizes, int n_in,
                              void* d_out, int out_size)
{
    (void)in_sizes; (void)n_in; (void)out_size;
    const float* x = (const float*)d_in[0];
    const float* W = (const float*)d_in[1];
    float* out = (float*)d_out;

    static int smem_set = 0;
    const int smem_bytes = SMEM_FLOATS * sizeof(float);
    if (!smem_set) {
        cudaFuncSetAttribute(caps_route_kernel,
                             cudaFuncAttributeMaxDynamicSharedMemorySize,
                             smem_bytes);
        smem_set = 1;
    }

    dim3 grid(NB / BT, NC);
    caps_route_kernel<<<grid, THREADS, smem_bytes>>>(x, W, out);
}

// round 6
// speedup vs baseline: 2.7448x; 1.1460x over previous
#include <cuda_runtime.h>

// CapsuleLayer dynamic routing — direct-LDG W, fused iter0 sum, 1024 threads, BT=2.
// x: [256, 1152, 8] f32 ; W: [10, 1152, 8, 16] f32 ; out: [256, 10, 16] f32
#define NB 256
#define NC 10
#define NR 1152
#define IC 8
#define OC 16
#define THREADS 1024
#define NWARP 32
#define BT 2
#define PSTR 1154                 // P row stride (floats), ≡2 mod 32
#define P_FLOATS (OC * PSTR)      // 18464, ≡0 mod 32
#define NUM_ITER 3

// SMEM floats:
//   P0[16][PSTR] | pad4 | P1[16][PSTR] | E0[NR] | E1[NR] | red2[32*33] |
//   S[32] | V[32] | red[64] | aux[8]
#define SMEM_FLOATS (2 * P_FLOATS + 4 + 2 * NR + 32 * 33 + 32 + 32 + 64 + 8)

extern "C" __global__ void __launch_bounds__(THREADS, 1)
caps_route_kernel(const float* __restrict__ x,
                  const float* __restrict__ W,
                  float* __restrict__ out)
{
    extern __shared__ float sm[];
    float* P0   = sm;
    float* P1   = P0 + P_FLOATS + 4;      // +4: batch-disjoint store banks
    float* E0   = P1 + P_FLOATS;
    float* E1   = E0 + NR;
    float* red2 = E1 + NR;                // [32][33]
    float* S    = red2 + 32 * 33;
    float* V    = S + 32;                 // [bb*16 + oc], 16B aligned
    float* red  = V + 32;
    float* aux  = red + 64;

    const int tid  = threadIdx.x;
    const int lane = tid & 31;
    const int wid  = tid >> 5;

    const int b0 = blockIdx.x * BT;
    const int c  = blockIdx.y;

    const float*  xb0 = x + (size_t)b0 * NR * IC;
    const float*  xb1 = xb0 + NR * IC;
    const float4* Wc4 = reinterpret_cast<const float4*>(
                            W + (size_t)c * NR * IC * OC);

    // ============ Phase 1: priors, direct-LDG W, fused iter0 column sums =====
    // thread = (row_l = tid>>3, sub = (tid>>1)&3, bb = tid&1); 9 rows/thread.
    {
        const int row_l = tid >> 3;
        const int sub   = (tid >> 1) & 3;
        const int bb    = tid & 1;
        const float* xb = bb ? xb1 : xb0;
        float*       P  = bb ? P1 : P0;

        float s0 = 0.f, s1 = 0.f, s2 = 0.f, s3 = 0.f;   // iter0 partial sums

        #pragma unroll 3
        for (int it = 0; it < 9; ++it) {
            const int r = row_l + it * 128;
            const float4* wp = Wc4 + (size_t)r * 32 + sub;
            const float4 xv0 = reinterpret_cast<const float4*>(xb + r * IC)[0];
            const float4 xv1 = reinterpret_cast<const float4*>(xb + r * IC)[1];
            const float4 w0 = wp[0];
            const float4 w1 = wp[4];
            const float4 w2 = wp[8];
            const float4 w3 = wp[12];
            const float4 w4 = wp[16];
            const float4 w5 = wp[20];
            const float4 w6 = wp[24];
            const float4 w7 = wp[28];

            float a0, a1, a2, a3;
            a0 = xv0.x * w0.x; a1 = xv0.x * w0.y; a2 = xv0.x * w0.z; a3 = xv0.x * w0.w;
            a0 = fmaf(xv0.y, w1.x, a0); a1 = fmaf(xv0.y, w1.y, a1);
            a2 = fmaf(xv0.y, w1.z, a2); a3 = fmaf(xv0.y, w1.w, a3);
            a0 = fmaf(xv0.z, w2.x, a0); a1 = fmaf(xv0.z, w2.y, a1);
            a2 = fmaf(xv0.z, w2.z, a2); a3 = fmaf(xv0.z, w2.w, a3);
            a0 = fmaf(xv0.w, w3.x, a0); a1 = fmaf(xv0.w, w3.y, a1);
            a2 = fmaf(xv0.w, w3.z, a2); a3 = fmaf(xv0.w, w3.w, a3);
            a0 = fmaf(xv1.x, w4.x, a0); a1 = fmaf(xv1.x, w4.y, a1);
            a2 = fmaf(xv1.x, w4.z, a2); a3 = fmaf(xv1.x, w4.w, a3);
            a0 = fmaf(xv1.y, w5.x, a0); a1 = fmaf(xv1.y, w5.y, a1);
            a2 = fmaf(xv1.y, w5.z, a2); a3 = fmaf(xv1.y, w5.w, a3);
            a0 = fmaf(xv1.z, w6.x, a0); a1 = fmaf(xv1.z, w6.y, a1);
            a2 = fmaf(xv1.z, w6.z, a2); a3 = fmaf(xv1.z, w6.w, a3);
            a0 = fmaf(xv1.w, w7.x, a0); a1 = fmaf(xv1.w, w7.y, a1);
            a2 = fmaf(xv1.w, w7.z, a2); a3 = fmaf(xv1.w, w7.w, a3);

            const int ob = sub * 4;
            P[(ob + 0) * PSTR + r] = a0;
            P[(ob + 1) * PSTR + r] = a1;
            P[(ob + 2) * PSTR + r] = a2;
            P[(ob + 3) * PSTR + r] = a3;
            s0 += a0; s1 += a1; s2 += a2; s3 += a3;
        }

        // reduce iter0 sums over row bits (lane bits 3,4)
        #pragma unroll
        for (int off = 8; off <= 16; off <<= 1) {
            s0 += __shfl_xor_sync(0xFFFFFFFFu, s0, off);
            s1 += __shfl_xor_sync(0xFFFFFFFFu, s1, off);
            s2 += __shfl_xor_sync(0xFFFFFFFFu, s2, off);
            s3 += __shfl_xor_sync(0xFFFFFFFFu, s3, off);
        }
        if (lane < 8) {
            const int sidx = (lane & 1) * 16 + ((lane >> 1) & 3) * 4;
            red2[wid * 33 + sidx + 0] = s0;
            red2[wid * 33 + sidx + 1] = s1;
            red2[wid * 33 + sidx + 2] = s2;
            red2[wid * 33 + sidx + 3] = s3;
        }
    }
    __syncthreads();

    // ============ iter 0: squash directly from phase-1 sums ==================
    const float inv_nr = 1.0f / (float)NR;
    if (wid == 0) {
        float s = 0.f;
        #pragma unroll
        for (int w2 = 0; w2 < 32; ++w2) s += red2[w2 * 33 + lane];
        float sv = s * inv_nr;
        float sq = sv * sv;
        #pragma unroll
        for (int off = 8; off > 0; off >>= 1)
            sq += __shfl_xor_sync(0xFFFFFFFFu, sq, off);   // within 16-lane half
        const float sc = sq / ((1.f + sq) * sqrtf(sq));
        V[lane] = sv * sc;
    }
    __syncthreads();

    // ============ Phase 2: routing iterations 1..2 ===========================
    // Thread owns logit row ra = tid; threads 0..127 also own rb = tid + 1024.
    const int  ra   = tid;
    const int  rb   = tid + THREADS;
    const bool hasb = (tid < NR - THREADS);   // tid < 128

    float La0 = 0.f, La1 = 0.f;   // logits row ra (b0, b1)
    float Lb0 = 0.f, Lb1 = 0.f;   // logits row rb

    const int wbb = wid >> 4;      // WS: warp -> (batch, oc)
    const int woc = wid & 15;
    const float* wsP = (wbb ? P1 : P0) + woc * PSTR;
    const float* wsE = wbb ? E1 : E0;

    for (int iter = 1; iter < NUM_ITER; ++iter) {
        // ---- delta logits for previous iteration (reads V) ----
        {
            const float4* V4 = reinterpret_cast<const float4*>(V);
            float da0 = 0.f, da1 = 0.f, db0 = 0.f, db1 = 0.f;
            #pragma unroll
            for (int o4 = 0; o4 < 4; ++o4) {
                const float4 v0 = V4[o4];
                const float4 v1 = V4[4 + o4];
                const float* p0 = P0 + (o4 * 4) * PSTR;
                const float* p1 = P1 + (o4 * 4) * PSTR;
                da0 = fmaf(p0[0 * PSTR + ra], v0.x, da0);
                da0 = fmaf(p0[1 * PSTR + ra], v0.y, da0);
                da0 = fmaf(p0[2 * PSTR + ra], v0.z, da0);
                da0 = fmaf(p0[3 * PSTR + ra], v0.w, da0);
                da1 = fmaf(p1[0 * PSTR + ra], v1.x, da1);
                da1 = fmaf(p1[1 * PSTR + ra], v1.y, da1);
                da1 = fmaf(p1[2 * PSTR + ra], v1.z, da1);
                da1 = fmaf(p1[3 * PSTR + ra], v1.w, da1);
                if (hasb) {
                    db0 = fmaf(p0[0 * PSTR + rb], v0.x, db0);
                    db0 = fmaf(p0[1 * PSTR + rb], v0.y, db0);
                    db0 = fmaf(p0[2 * PSTR + rb], v0.z, db0);
                    db0 = fmaf(p0[3 * PSTR + rb], v0.w, db0);
                    db1 = fmaf(p1[0 * PSTR + rb], v1.x, db1);
                    db1 = fmaf(p1[1 * PSTR + rb], v1.y, db1);
                    db1 = fmaf(p1[2 * PSTR + rb], v1.z, db1);
                    db1 = fmaf(p1[3 * PSTR + rb], v1.w, db1);
                }
            }
            La0 += da0; La1 += da1;
            Lb0 += db0; Lb1 += db1;
        }

        // ---- softmax over r (both batches) ----
        {
            float m0 = La0, m1 = La1;
            if (hasb) { m0 = fmaxf(m0, Lb0); m1 = fmaxf(m1, Lb1); }
            #pragma unroll
            for (int off = 16; off > 0; off >>= 1) {
                m0 = fmaxf(m0, __shfl_xor_sync(0xFFFFFFFFu, m0, off));
                m1 = fmaxf(m1, __shfl_xor_sync(0xFFFFFFFFu, m1, off));
            }
            if (lane == 0) { red[wid] = m0; red[32 + wid] = m1; }
            __syncthreads();
            if (wid < 2) {
                float v = red[wid * 32 + lane];
                #pragma unroll
                for (int off = 16; off > 0; off >>= 1)
                    v = fmaxf(v, __shfl_xor_sync(0xFFFFFFFFu, v, off));
                if (lane == 0) aux[wid] = v;
            }
            __syncthreads();
            m0 = aux[0]; m1 = aux[1];

            float s0, s1;
            {
                const float ea0 = __expf(La0 - m0);
                const float ea1 = __expf(La1 - m1);
                E0[ra] = ea0; E1[ra] = ea1;
                s0 = ea0; s1 = ea1;
                if (hasb) {
                    const float eb0 = __expf(Lb0 - m0);
                    const float eb1 = __expf(Lb1 - m1);
                    E0[rb] = eb0; E1[rb] = eb1;
                    s0 += eb0; s1 += eb1;
                }
            }
            #pragma unroll
            for (int off = 16; off > 0; off >>= 1) {
                s0 += __shfl_xor_sync(0xFFFFFFFFu, s0, off);
                s1 += __shfl_xor_sync(0xFFFFFFFFu, s1, off);
            }
            if (lane == 0) { red[wid] = s0; red[32 + wid] = s1; }
            __syncthreads();
            if (wid < 2) {
                float v = red[wid * 32 + lane];
                #pragma unroll
                for (int off = 16; off > 0; off >>= 1)
                    v += __shfl_xor_sync(0xFFFFFFFFu, v, off);
                if (lane == 0) aux[2 + wid] = 1.0f / v;
            }
            __syncthreads();   // E + aux visible to all
        }

        // ---- weighted sum: one warp per (batch, oc), stride-1 scans ----
        {
            float a = 0.f;
            #pragma unroll 4
            for (int rr = lane; rr < NR; rr += 32)
                a = fmaf(wsE[rr], wsP[rr], a);
            #pragma unroll
            for (int off = 16; off > 0; off >>= 1)
                a += __shfl_xor_sync(0xFFFFFFFFu, a, off);
            if (lane == 0) S[wid] = a;
        }
        __syncthreads();

        // ---- squash (warp 0; lanes 0-15 b0, 16-31 b1) ----
        if (wid == 0) {
            float sv = S[lane] * aux[2 + (lane >> 4)];
            float sq = sv * sv;
            #pragma unroll
            for (int off = 8; off > 0; off >>= 1)
                sq += __shfl_xor_sync(0xFFFFFFFFu, sq, off);
            const float sc = sq / ((1.f + sq) * sqrtf(sq));
            V[lane] = sv * sc;
        }
        __syncthreads();
    }

    // ============ Phase 3: output ============================================
    if (tid < 2 * OC) {
        const int obb = tid >> 4;
        out[((size_t)(b0 + obb) * NC + c) * OC + (tid & 15)] = V[tid];
    }
}

extern "C" void kernel_launch(void* const* d_in, const int* in_sizes, int n_in,
                              void* d_out, int out_size)
{
    (void)in_sizes; (void)n_in; (void)out_size;
    const float* x = (const float*)d_in[0];
    const float* W = (const float*)d_in[1];
    float* out = (float*)d_out;

    static int smem_set = 0;
    const int smem_bytes = SMEM_FLOATS * sizeof(float);
    if (!smem_set) {
        cudaFuncSetAttribute(caps_route_kernel,
                             cudaFuncAttributeMaxDynamicSharedMemorySize,
                             smem_bytes);
        smem_set = 1;
    }

    dim3 grid(NB / BT, NC);
    caps_route_kernel<<<grid, THREADS, smem_bytes>>>(x, W, out);
}